// round 17
// baseline (speedup 1.0000x reference)
#include <cuda_runtime.h>
#include <cstdint>

// Problem constants (fixed-shape problem)
#define BB   8
#define CCH  128
#define HH   96
#define WW   160
#define DNUM 81

// Tiling
#define TXW   32          // x pixels per block
#define CC    8           // channels per pipeline chunk
#define NCHUNK (CCH / CC) // 16

#define TWO_ROWS  16      // (8 y pixels + 2*4 halo)
#define TWO_PITCH 40      // (32 x + 2*4 halo)
#define ONE_ROWS  8

#define TWO_STAGE_FLOATS (CC * TWO_ROWS * TWO_PITCH)  // 5120
#define ONE_STAGE_FLOATS (CC * ONE_ROWS * TXW)        // 2048
#define SMEM_FLOATS (2 * (TWO_STAGE_FLOATS + ONE_STAGE_FLOATS)) // 14336
#define SMEM_BYTES  (SMEM_FLOATS * 4)                 // 57344

typedef unsigned long long u64;

// Packed f32x2 FMA: d.{lo,hi} += a.{lo,hi} * b.{lo,hi}  (IEEE fma per lane)
__device__ __forceinline__ void ffma2(u64& d, u64 a, u64 b) {
    asm("fma.rn.f32x2 %0, %1, %2, %0;" : "+l"(d) : "l"(a), "l"(b));
}
__device__ __forceinline__ float f2lo(u64 v) { return __uint_as_float((unsigned)v); }
__device__ __forceinline__ float f2hi(u64 v) { return __uint_as_float((unsigned)(v >> 32)); }

__device__ __forceinline__ void cp16(uint32_t dst, const void* src, int src_bytes) {
    // 16-byte cp.async with ignore-src zero-fill (src_bytes = 0 -> all zeros)
    asm volatile("cp.async.cg.shared.global [%0], [%1], 16, %2;\n"
                 :: "r"(dst), "l"(src), "r"(src_bytes));
}

__device__ __forceinline__ void load_chunk(
    const float* __restrict__ one, const float* __restrict__ two,
    float* two_s, float* one_s,
    int stage, int ccBase, int b, int yb, int x0, int tid)
{
    // ---- two tile: CC x 16 rows x 40 cols = 1280 16B-chunks, 10 per thread ----
    #pragma unroll
    for (int i = 0; i < 10; i++) {
        int t   = tid + i * 128;
        int c   = t / 160;
        int rem = t - c * 160;
        int r   = rem / 10;
        int q   = rem - r * 10;
        int y2  = yb - 4 + r;
        int xs  = x0 - 4 + q * 4;
        bool ok = (y2 >= 0) && (y2 < HH) && (xs >= 0) && (xs <= WW - 4);
        int yc  = min(max(y2, 0), HH - 1);
        int xc  = min(max(xs, 0), WW - 4);
        const float* g = two + (((size_t)b * CCH + ccBase + c) * HH + yc) * WW + xc;
        float* dptr = &two_s[((stage * CC + c) * TWO_ROWS + r) * TWO_PITCH + q * 4];
        uint32_t dst = (uint32_t)__cvta_generic_to_shared(dptr);
        cp16(dst, g, ok ? 16 : 0);
    }
    // ---- one tile: CC x 8 rows x 32 cols = 512 16B-chunks, 4 per thread ----
    #pragma unroll
    for (int i = 0; i < 4; i++) {
        int t   = tid + i * 128;
        int c   = t / 64;
        int rem = t - c * 64;
        int r   = rem / 8;
        int q   = rem - r * 8;
        const float* g = one + (((size_t)b * CCH + ccBase + c) * HH + yb + r) * WW + x0 + q * 4;
        float* dptr = &one_s[((stage * CC + c) * ONE_ROWS + r) * TXW + q * 4];
        uint32_t dst = (uint32_t)__cvta_generic_to_shared(dptr);
        cp16(dst, g, 16);
    }
    asm volatile("cp.async.commit_group;\n");
}

__global__ void __launch_bounds__(128, 2)
ModuleCorrelation_5669356831807_kernel(
    const float* __restrict__ one,
    const float* __restrict__ two,
    float* __restrict__ out)
{
    extern __shared__ float smem[];
    float* two_s = smem;                        // [2][CC][16][40]
    float* one_s = smem + 2 * TWO_STAGE_FLOATS; // [2][CC][8][32]

    const int tid  = threadIdx.x;      // 0..127
    const int lane = tid & 31;
    const int w    = tid >> 5;         // warp 0..3
    // Each thread owns an x-PAIR (x, x+1) at one y:
    //   lanes 0..15  -> y row 2w,   x-pairs 0,2,...,30
    //   lanes 16..31 -> y row 2w+1, x-pairs 0,2,...,30
    const int yrow  = 2 * w + (lane >> 4);   // 0..7
    const int xpair = (lane & 15) * 2;       // 0,2,...,30

    const int x0 = blockIdx.x * TXW;
    const int yb = blockIdx.y * 8;
    const int b  = blockIdx.z;

    // Even x-displacements (j=2k): packed {pix_x, pix_x+1} f32x2 accumulators.
    // Odd  x-displacements (j=2k+1): scalar float2 accumulators.
    u64    accE[45];   // index p*5 + k  -> d = p*9 + 2k
    float2 accO[36];   // index p*4 + k  -> d = p*9 + 2k + 1
    #pragma unroll
    for (int i = 0; i < 45; i++) accE[i] = 0ull;
    #pragma unroll
    for (int i = 0; i < 36; i++) accO[i] = make_float2(0.f, 0.f);

    // Prologue: stage chunk 0
    load_chunk(one, two, two_s, one_s, 0, 0, b, yb, x0, tid);

    for (int ch = 0; ch < NCHUNK; ch++) {
        const int s = ch & 1;
        asm volatile("cp.async.wait_group 0;\n" ::: "memory");
        __syncthreads();  // chunk ch visible; prev compute done

        if (ch + 1 < NCHUNK)
            load_chunk(one, two, two_s, one_s, s ^ 1, (ch + 1) * CC, b, yb, x0, tid);

        const float* ts = &two_s[(s * CC) * (TWO_ROWS * TWO_PITCH) + yrow * TWO_PITCH + xpair];
        const float* os = &one_s[(s * CC) * (ONE_ROWS * TXW) + yrow * TXW + xpair];

        #pragma unroll
        for (int c = 0; c < CC; c++) {
            const u64 onep = *(const u64*)(os + c * (ONE_ROWS * TXW)); // {one[x], one[x+1]}
            const float one0 = f2lo(onep);
            const float one1 = f2hi(onep);
            const float* tpc = ts + c * (TWO_ROWS * TWO_PITCH);
            #pragma unroll
            for (int p = 0; p < 9; p++) {
                // Row (yrow + p) of two tile, cols xpair .. xpair+9 as 5 aligned LDS.64
                const u64* rp = (const u64*)(tpc + p * TWO_PITCH);
                u64 P0 = rp[0], P1 = rp[1], P2 = rp[2], P3 = rp[3], P4 = rp[4];
                // even j = 2k: acc{x,x+1} += {one0,one1} * {v[2k], v[2k+1]}
                ffma2(accE[p * 5 + 0], onep, P0);
                ffma2(accE[p * 5 + 1], onep, P1);
                ffma2(accE[p * 5 + 2], onep, P2);
                ffma2(accE[p * 5 + 3], onep, P3);
                ffma2(accE[p * 5 + 4], onep, P4);
                // odd j = 2k+1: pix_x uses v[2k+1] = hi(Pk), pix_x+1 uses v[2k+2] = lo(Pk+1)
                accO[p * 4 + 0].x = fmaf(one0, f2hi(P0), accO[p * 4 + 0].x);
                accO[p * 4 + 0].y = fmaf(one1, f2lo(P1), accO[p * 4 + 0].y);
                accO[p * 4 + 1].x = fmaf(one0, f2hi(P1), accO[p * 4 + 1].x);
                accO[p * 4 + 1].y = fmaf(one1, f2lo(P2), accO[p * 4 + 1].y);
                accO[p * 4 + 2].x = fmaf(one0, f2hi(P2), accO[p * 4 + 2].x);
                accO[p * 4 + 2].y = fmaf(one1, f2lo(P3), accO[p * 4 + 2].y);
                accO[p * 4 + 3].x = fmaf(one0, f2hi(P3), accO[p * 4 + 3].x);
                accO[p * 4 + 3].y = fmaf(one1, f2lo(P4), accO[p * 4 + 3].y);
            }
        }
    }

    // Epilogue: out[b, d, y, x] with plane stride H*W; store float2 per d (x, x+1)
    const int y = yb + yrow;
    const int x = x0 + xpair;
    const float inv = 1.0f / (float)CCH;
    const size_t plane = (size_t)HH * WW;
    float* obase = out + ((size_t)b * DNUM) * plane + (size_t)y * WW + x;
    #pragma unroll
    for (int p = 0; p < 9; p++) {
        #pragma unroll
        for (int k = 0; k < 5; k++) {
            const int d = p * 9 + 2 * k;
            const u64 a = accE[p * 5 + k];
            *(float2*)(obase + (size_t)d * plane) = make_float2(f2lo(a) * inv, f2hi(a) * inv);
        }
        #pragma unroll
        for (int k = 0; k < 4; k++) {
            const int d = p * 9 + 2 * k + 1;
            const float2 a = accO[p * 4 + k];
            *(float2*)(obase + (size_t)d * plane) = make_float2(a.x * inv, a.y * inv);
        }
    }
}

extern "C" void kernel_launch(void* const* d_in, const int* in_sizes, int n_in,
                              void* d_out, int out_size) {
    const float* one = (const float*)d_in[0];
    const float* two = (const float*)d_in[1];
    float* out = (float*)d_out;

    // >48KB dynamic smem requires opt-in (idempotent, graph-capture safe)
    cudaFuncSetAttribute(ModuleCorrelation_5669356831807_kernel,
                         cudaFuncAttributeMaxDynamicSharedMemorySize, SMEM_BYTES);

    dim3 grid(WW / TXW, HH / 8, BB);  // (5, 12, 8) = 480 blocks
    dim3 blk(128);
    ModuleCorrelation_5669356831807_kernel<<<grid, blk, SMEM_BYTES>>>(one, two, out);
}